// round 17
// baseline (speedup 1.0000x reference)
#include <cuda_runtime.h>
#include <cuda_fp16.h>
#include <cstdint>

#define NPTS 16384
#define DIM  64
#define MB   32                  // rows per CTA
#define NBT  256                 // cols per tile
#define NT   512                 // threads (16 warps)
#define NTILES (NPTS / NBT)      // 64 col tiles total
#define FINF 3.402823466e38f

__device__ float g_sq[NPTS];
__device__ unsigned long long g_key[NPTS];
__device__ uint4 g_bf4[262144];          // 4MB fragment-major fp16 2-plane X (A and B)

// ---------------- helpers ----------------
#define MMA16(c, a0, a1, a2, a3, b0, b1) \
    asm volatile("mma.sync.aligned.m16n8k16.row.col.f32.f16.f16.f32 " \
        "{%0,%1,%2,%3},{%4,%5,%6,%7},{%8,%9},{%0,%1,%2,%3};" \
        : "+f"((c)[0]), "+f"((c)[1]), "+f"((c)[2]), "+f"((c)[3]) \
        : "r"(a0), "r"(a1), "r"(a2), "r"(a3), "r"(b0), "r"(b1))

__device__ __forceinline__ void stz16(float* p) {
    asm volatile("st.global.cs.v4.f32 [%0], {%1,%1,%1,%1};" :: "l"(p), "f"(0.f) : "memory");
}

__device__ __forceinline__ uint32_t pack_plane(float2 v, int p) {
    __half h0x = __float2half_rn(v.x);
    __half h0y = __float2half_rn(v.y);
    __half lx, ly;
    if (p == 0) { lx = h0x; ly = h0y; }
    else {
        lx = __float2half_rn(v.x - __half2float(h0x));
        ly = __float2half_rn(v.y - __half2float(h0y));
    }
    return (uint32_t)__half_as_ushort(lx) | ((uint32_t)__half_as_ushort(ly) << 16);
}

__device__ __forceinline__ unsigned long long mkkey(float v, int idx) {
    uint32_t b = __float_as_uint(v);
    b ^= (uint32_t)(((int32_t)b >> 31)) | 0x80000000u;   // monotonic map
    return ((unsigned long long)b << 32) | (unsigned)idx;
}

// ---------------- small kernels ----------------
__global__ void sq_kernel(const float* __restrict__ X) {
    int warp = (blockIdx.x * blockDim.x + threadIdx.x) >> 5;
    int lane = threadIdx.x & 31;
    if (warp >= NPTS) return;
    const float* row = X + (size_t)warp * DIM;
    float a = row[lane], b = row[lane + 32];
    float s = a * a + b * b;
    #pragma unroll
    for (int o = 16; o; o >>= 1) s += __shfl_xor_sync(0xffffffffu, s, o);
    if (lane == 0) { g_sq[warp] = s; g_key[warp] = 0xFFFFFFFFFFFFFFFFull; }
}

// fragment-major fp16 planes: uint4 index = (((tile*4+s)*2+p)*8+npair)*32+lane
__global__ void prep_b(const float* __restrict__ X) {
    int gid = blockIdx.x * blockDim.x + threadIdx.x;   // 0..262143
    int lane = gid & 31;
    int r1 = gid >> 5;
    int npair = r1 & 7;
    int r2 = r1 >> 3;
    int p = r2 & 1;
    int r3 = r2 >> 1;
    int s = r3 & 3;
    int tile = r3 >> 2;
    int lg = lane >> 2, lt = lane & 3;
    int j0 = tile * 128 + npair * 16 + lg;
    int j1 = j0 + 8;
    int kb = s * 16 + 2 * lt;
    float2 e00 = *(const float2*)(X + (size_t)j0 * DIM + kb);
    float2 e01 = *(const float2*)(X + (size_t)j0 * DIM + kb + 8);
    float2 e10 = *(const float2*)(X + (size_t)j1 * DIM + kb);
    float2 e11 = *(const float2*)(X + (size_t)j1 * DIM + kb + 8);
    uint4 o;
    o.x = pack_plane(e00, p);
    o.y = pack_plane(e01, p);
    o.z = pack_plane(e10, p);
    o.w = pack_plane(e11, p);
    g_bf4[gid] = o;
}

__global__ void final_kernel(float* __restrict__ out) {
    int row = blockIdx.x * blockDim.x + threadIdx.x;
    unsigned idx = (unsigned)(g_key[row] & 0xFFFFFFFFu);
    out[(size_t)row * NPTS + row] = 1.0f;
    out[(size_t)row * NPTS + idx] = 1.0f;
}

// ---------------- epilogue (GUARD=1 only on the diagonal tile) ----------------
#define EPILOGUE(GUARD)                                                           \
    {                                                                             \
        /* row-side: fmin tree + rare record scan */                              \
        _Pragma("unroll")                                                         \
        for (int h = 0; h < 2; h++) {                                             \
            const int ig = row0 + wm * 16 + lg + h * 8;                           \
            float m = FINF;                                                       \
            _Pragma("unroll")                                                     \
            for (int nf = 0; nf < 4; nf++) {                                      \
                float v0 = fmaf(-2.f, acc[nf][2 * h], sb[nf].x);                  \
                float v1 = fmaf(-2.f, acc[nf][2 * h + 1], sb[nf].y);              \
                if (GUARD) {                                                      \
                    int jj = cb + cg * 32 + nf * 8 + 2 * lt;                      \
                    if (jj == ig) v0 = FINF;                                      \
                    if (jj + 1 == ig) v1 = FINF;                                  \
                }                                                                 \
                m = fminf(m, fminf(v0, v1));                                      \
            }                                                                     \
            if (m < mn[h]) {                                                      \
                mn[h] = m;                                                        \
                _Pragma("unroll")                                                 \
                for (int nf = 3; nf >= 0; nf--) {                                 \
                    int jj = cb + cg * 32 + nf * 8 + 2 * lt;                      \
                    float v1 = fmaf(-2.f, acc[nf][2 * h + 1], sb[nf].y);          \
                    if (v1 == m) mi[h] = jj + 1;                                  \
                    float v0 = fmaf(-2.f, acc[nf][2 * h], sb[nf].x);              \
                    if (v0 == m) mi[h] = jj;                                      \
                }                                                                 \
            }                                                                     \
        }                                                                         \
        /* col-side: f32 shfl-min tree + ballot index extraction */               \
        _Pragma("unroll")                                                         \
        for (int nf = 0; nf < 4; nf++) {                                          \
            _Pragma("unroll")                                                     \
            for (int c = 0; c < 2; c++) {                                         \
                const int j = cb + cg * 32 + nf * 8 + 2 * lt + c;                 \
                float va = fmaf(-2.f, acc[nf][c], saA);                           \
                float vb = fmaf(-2.f, acc[nf][2 + c], saB);                       \
                if (GUARD) {                                                      \
                    if (j == rgA) va = FINF;                                      \
                    if (j == rgB) vb = FINF;                                      \
                }                                                                 \
                float v = fminf(va, vb);                                          \
                v = fminf(v, __shfl_xor_sync(0xffffffffu, v, 4));                 \
                v = fminf(v, __shfl_xor_sync(0xffffffffu, v, 8));                 \
                v = fminf(v, __shfl_xor_sync(0xffffffffu, v, 16));                \
                bool hit = (va == v) || (vb == v);                                \
                int cand = (va == v) ? rgA : rgB;                                 \
                unsigned msk = __ballot_sync(0xffffffffu, hit) & (0x11111111u << lt); \
                int widx = __shfl_sync(0xffffffffu, cand, __ffs(msk) - 1);        \
                if (lg == 0) atomicMin(&g_key[j], mkkey(v, widx));                \
            }                                                                     \
        }                                                                         \
    }

// ---------------- main kernel: symmetric upper-triangle sweep ----------------
__global__ void __launch_bounds__(NT, 1)
knn_kernel(float* __restrict__ out) {
    __shared__ unsigned long long skey[MB][8];

    const int tid  = threadIdx.x;
    const int lane = tid & 31;
    const int wid  = tid >> 5;
    const int wm   = wid >> 3;          // 0..1 -> rows wm*16
    const int cg   = wid & 7;           // 0..7 -> cols cg*32
    const int lg   = lane >> 2;         // 0..7
    const int lt   = lane & 3;          // 0..3
    const int row0 = blockIdx.x * MB;
    const int ct0  = blockIdx.x >> 3;   // first col tile: align_down(row0,256)/256

    // ---- A fragments: resident in registers ----
    uint4 a[2][4];                       // [plane][stage]
    {
        const int rbA = blockIdx.x * 2 + wm;
        const int tA = rbA >> 3, npA = rbA & 7;
        #pragma unroll
        for (int s = 0; s < 4; s++)
            #pragma unroll
            for (int p = 0; p < 2; p++)
                a[p][s] = g_bf4[((((tA * 4 + s) * 2) + p) * 8 + npA) * 32 + lane];
    }

    const int rgA = row0 + wm * 16 + lg;
    const int rgB = rgA + 8;
    const float saA = g_sq[rgA];
    const float saB = g_sq[rgB];

    // B base pointer (immediate offsets inside tile)
    const uint4* bp = g_bf4
        + (size_t)(ct0 * 2 + (cg >> 2)) * 2048
        + (cg & 3) * 64 + lane;

    float mn[2];
    int   mi[2];
    mn[0] = mn[1] = FINF;
    mi[0] = mi[1] = 0;

    // prologue: prefetch stages 0,1 of first tile
    uint4 Bb[2][2][2];                   // [buf][plane][pp]
    #pragma unroll
    for (int p = 0; p < 2; p++)
        #pragma unroll
        for (int pp = 0; pp < 2; pp++) {
            Bb[0][p][pp] = bp[0 * 512 + p * 256 + pp * 32];
            Bb[1][p][pp] = bp[1 * 512 + p * 256 + pp * 32];
        }

    for (int ct = ct0; ct < NTILES; ct++) {
        const int cb = ct * NBT;

        // prefetch sq-norms for this tile's cols
        float2 sb[4];
        #pragma unroll
        for (int nf = 0; nf < 4; nf++)
            sb[nf] = __ldg((const float2*)&g_sq[cb + cg * 32 + nf * 8 + 2 * lt]);

        float acc[4][4];
        #pragma unroll
        for (int nf = 0; nf < 4; nf++)
            #pragma unroll
            for (int r = 0; r < 4; r++) acc[nf][r] = 0.f;

        #pragma unroll
        for (int s = 0; s < 4; s++) {
            const int cur = s & 1;
            #pragma unroll
            for (int nf = 0; nf < 4; nf++) {
                const uint4& B = Bb[cur][0][nf >> 1];
                MMA16(acc[nf], a[0][s].x, a[0][s].z, a[0][s].y, a[0][s].w,
                      (nf & 1) ? B.z : B.x, (nf & 1) ? B.w : B.y);
            }
            #pragma unroll
            for (int nf = 0; nf < 4; nf++) {
                const uint4& B = Bb[cur][1][nf >> 1];
                MMA16(acc[nf], a[0][s].x, a[0][s].z, a[0][s].y, a[0][s].w,
                      (nf & 1) ? B.z : B.x, (nf & 1) ? B.w : B.y);
            }
            #pragma unroll
            for (int nf = 0; nf < 4; nf++) {
                const uint4& B = Bb[cur][0][nf >> 1];
                MMA16(acc[nf], a[1][s].x, a[1][s].z, a[1][s].y, a[1][s].w,
                      (nf & 1) ? B.z : B.x, (nf & 1) ? B.w : B.y);
            }
            // depth-2 WAR-ring prefetch
            if (s < 2) {
                #pragma unroll
                for (int p = 0; p < 2; p++)
                    #pragma unroll
                    for (int pp = 0; pp < 2; pp++)
                        Bb[cur][p][pp] = bp[(s + 2) * 512 + p * 256 + pp * 32];
            } else if (ct + 1 < NTILES) {
                #pragma unroll
                for (int p = 0; p < 2; p++)
                    #pragma unroll
                    for (int pp = 0; pp < 2; pp++)
                        Bb[cur][p][pp] = bp[4096 + (s - 2) * 512 + p * 256 + pp * 32];
            }
        }
        bp += 4096;

        if (ct == ct0) {
            EPILOGUE(1);
        } else {
            EPILOGUE(0);
        }

        // ---- zero-fill main 32x256 tile (+ mirror when off-diagonal) ----
        {
            float* p = out + (size_t)(row0 + (tid >> 4)) * NPTS + cb + (tid & 15) * 4;
            #pragma unroll
            for (int i = 0; i < 4; i++) stz16(p + i * 64);
            if (ct != ct0) {
                #pragma unroll
                for (int i = 0; i < 4; i++) {
                    int g = i * NT + tid;
                    int mr = g >> 3, q = g & 7;
                    stz16(out + (size_t)(cb + mr) * NPTS + row0 + q * 4);
                }
            }
        }
    }

    // ---- row-side cross-warp reduction, then atomicMin merge ----
    #pragma unroll
    for (int h = 0; h < 2; h++) {
        unsigned long long k = mkkey(mn[h], mi[h]);
        unsigned long long o;
        o = __shfl_xor_sync(0xffffffffu, k, 1); if (o < k) k = o;
        o = __shfl_xor_sync(0xffffffffu, k, 2); if (o < k) k = o;
        if (lt == 0) skey[wm * 16 + h * 8 + lg][cg] = k;
    }
    __syncthreads();
    if (tid < MB) {
        unsigned long long k = skey[tid][0];
        #pragma unroll
        for (int x = 1; x < 8; x++) {
            unsigned long long o = skey[tid][x];
            if (o < k) k = o;
        }
        atomicMin(&g_key[row0 + tid], k);
    }
}

extern "C" void kernel_launch(void* const* d_in, const int* in_sizes, int n_in,
                              void* d_out, int out_size) {
    const float* X = (const float*)d_in[0];
    float* out = (float*)d_out;
    sq_kernel<<<NPTS / 8, 256>>>(X);
    prep_b<<<1024, 256>>>(X);
    knn_kernel<<<NPTS / MB, NT>>>(out);
    final_kernel<<<NPTS / 256, 256>>>(out);
}